// round 4
// baseline (speedup 1.0000x reference)
#include <cuda_runtime.h>
#include <cstdint>

#define TT 2048

__device__ __forceinline__ float ex2_ap (float x){ float r; asm("ex2.approx.f32 %0, %1;"  : "=f"(r) : "f"(x)); return r; }
__device__ __forceinline__ float rcp_ap (float x){ float r; asm("rcp.approx.f32 %0, %1;"  : "=f"(r) : "f"(x)); return r; }
__device__ __forceinline__ float sqrt_ap(float x){ float r; asm("sqrt.approx.f32 %0, %1;" : "=f"(r) : "f"(x)); return r; }
__device__ __forceinline__ float clampf(float x, float lo, float hi){ return fminf(fmaxf(x, lo), hi); }
__device__ __forceinline__ float relu(float x){ return fmaxf(x, 0.f); }

struct Consts {
  float insc, Cc, Sc, Sinv, kexp, sub, crak, rk, lg, kr, ls;
};

// One scan step + fused pass-2 output Q (valid for t>=1; t==0 patched after loop).
__device__ __forceinline__ float step(float4 v, float& SMS, float& GW, float& RS, const Consts& c)
{
  float Prec = v.x, PET = v.y, RSmax = v.z, Area = v.w;

  // interception (input-only, off-chain)
  float IMAX = fmaxf(fminf(c.insc, PET), 0.f);
  float INTC = fmaxf(fminf(IMAX, Prec), 0.f);
  float INR  = relu(Prec - INTC);
  float POT  = relu(PET - INTC);

  // SMS recurrence chain
  float SMS1c = fmaxf(fminf(SMS, c.Sc), 0.f);
  float ratio = SMS1c * c.Sinv;
  float infil = c.Cc * ex2_ap(c.kexp * SMS1c);
  float sr      = c.sub  * ratio;
  float one_msr = 1.f - sr;
  float cr      = c.crak * ratio;
  float one_mcr = 1.f - cr;
  float cap = 10.f * ratio;
  float ETS = fminf(POT, cap);
  float base = SMS1c - ETS;
  float baseS = base - c.Sc;

  float RMO  = fminf(INR, infil);
  float IRUN = INR - RMO;
  float SRUN = sr * RMO;
  float RmS  = one_msr * RMO;
  float REC  = cr * RmS;
  float SMF  = one_mcr * RmS;
  float SMSn = base + SMF;

  // recharge + gw
  float xr   = baseS + SMF;
  float RECn = REC + relu(xr);
  float BAS  = c.rk * relu(GW);
  float GWn  = (GW - c.lg - BAS) + RECn;

  // release with incoming RS
  float inflow = (IRUN + SRUN + BAS) * Area;
  float x5  = RS + inflow - RSmax;
  float Qor = relu(x5);
  float rcpR = rcp_ap(RSmax);
  float krRSmax = c.kr * RSmax;
  float r5 = relu(RS) * rcp_ap(RSmax);
  float p5 = r5 * sqrt_ap(r5);
  float Qir = (x5 > 0.f) ? krRSmax : (c.kr * RS * p5);
  float RSn = RS + (inflow - Qor - Qir);

  // pass-2 Q with POST-step RS
  float x6  = RSn + inflow - RSmax;
  float Qor2 = relu(x6);
  float r6 = relu(RSn) * rcpR;
  float p6 = r6 * sqrt_ap(r6);
  float Qir2 = (x6 > 0.f) ? krRSmax : (c.kr * RSn * p6);
  float onemA = 1.f - Area;
  float drarg = (SRUN + IRUN) * onemA + Qir2 + Qor2 - c.ls;
  float DR = relu(drarg);
  float Q = relu(DR + BAS * onemA);

  SMS = SMSn; GW = GWn; RS = RSn;
  return Q;
}

// Full pass-2 Q for t==0: rolled SMS/GW = FINAL states, RS = outs[b,0,2]
__device__ __forceinline__ float q_final(float4 v, float SMS1r, float GW1r, float RSr, const Consts& c)
{
  float Prec = v.x, PET = v.y, RSmax = v.z, Area = v.w;
  float IMAX = fmaxf(fminf(c.insc, PET), 0.f);
  float INTC = fmaxf(fminf(IMAX, Prec), 0.f);
  float INR  = relu(Prec - INTC);
  float SMS1c = fmaxf(fminf(SMS1r, c.Sc), 0.f);
  float infil = c.Cc * ex2_ap(c.kexp * SMS1c);
  float RMO = fminf(INR, infil);
  float IRUN = INR - RMO;
  float ratio = SMS1c * c.Sinv;
  float SRUN = c.sub * ratio * RMO;
  float BAS = c.rk * relu(GW1r);
  float inflow = (IRUN + SRUN + BAS) * Area;
  float x5 = RSr + inflow - RSmax;
  float Qor = relu(x5);
  float r = relu(RSr) * rcp_ap(RSmax);
  float pw = r * sqrt_ap(r);
  float Qir = (x5 > 0.f) ? (c.kr * RSmax) : (c.kr * RSr * pw);
  float drarg = (SRUN + IRUN) * (1.f - Area) + Qir + Qor - c.ls;
  float DR = relu(drarg);
  float GD = BAS * (1.f - Area);
  return relu(DR + GD);
}

__global__ void __launch_bounds__(32, 1)
hirnn_kernel(const float4* __restrict__ xin_all,
             const float* __restrict__ pINSC, const float* __restrict__ pCOEFF,
             const float* __restrict__ pSQ,   const float* __restrict__ pSMSC,
             const float* __restrict__ pSUB,  const float* __restrict__ pCRAK,
             const float* __restrict__ pRecK, const float* __restrict__ pKr,
             const float* __restrict__ pLG,   const float* __restrict__ pLS,
             float* __restrict__ out, int B)
{
  int H = B >> 1;
  int b = blockIdx.x * 32 + threadIdx.x;
  if (b >= H) return;

  Consts c;
  c.insc = clampf(pINSC[0] * 5.f, 0.5f, 5.f);
  c.Cc   = clampf(pCOEFF[0] * 400.f, 50.f, 400.f);
  float qv = clampf(pSQ[0] * 6.f, 0.f, 6.f);
  c.Sc   = clampf(pSMSC[0] * 500.f, 50.f, 500.f);
  c.Sinv = 1.f / c.Sc;
  c.kexp = -qv * c.Sinv * 1.4426950408889634f;   // exp(-q*s/S) == exp2(kexp*s)
  c.sub  = clampf(pSUB[0], 0.f, 1.f);
  c.crak = clampf(pCRAK[0], 0.f, 1.f);
  c.rk   = clampf(pRecK[0] * 0.3f, 0.003f, 0.3f);
  c.lg   = clampf(pLG[0] * 0.1f, 0.001f, 0.1f);
  c.kr   = clampf(pKr[0] * 0.1f, 0.01f, 0.1f);
  c.ls   = clampf(pLS[0] * 10.f, 0.01f, 10.f);

  const float4* __restrict__ x0p = xin_all + (size_t)b * TT;
  const float4* __restrict__ x1p = xin_all + (size_t)(b + H) * TT;
  float* __restrict__ o0 = out + (size_t)b * TT;
  float* __restrict__ o1 = out + (size_t)(b + H) * TT;

  float S0 = 0.f, G0 = 0.f, R0 = 0.f;
  float S1 = 0.f, G1 = 0.f, R1 = 0.f;
  float rs00 = 0.f, rs01 = 0.f;
  float4 first0, first1;

  float4 A0[4], A1[4], Bb0[4], Bb1[4];
#pragma unroll
  for (int i = 0; i < 4; i++) { A0[i] = x0p[i]; A1[i] = x1p[i]; }
  first0 = A0[0]; first1 = A1[0];

  for (int g = 0; g < TT; g += 8) {
    // ---- phase 1: prefetch [g+4, g+8), compute on A ----
#pragma unroll
    for (int i = 0; i < 4; i++) { Bb0[i] = x0p[g + 4 + i]; Bb1[i] = x1p[g + 4 + i]; }
    {
      float qa0, qa1, qa2, qa3, qb0, qb1, qb2, qb3;
      qa0 = step(A0[0], S0, G0, R0, c);  qb0 = step(A1[0], S1, G1, R1, c);
      if (g == 0) { rs00 = R0; rs01 = R1; }
      qa1 = step(A0[1], S0, G0, R0, c);  qb1 = step(A1[1], S1, G1, R1, c);
      qa2 = step(A0[2], S0, G0, R0, c);  qb2 = step(A1[2], S1, G1, R1, c);
      qa3 = step(A0[3], S0, G0, R0, c);  qb3 = step(A1[3], S1, G1, R1, c);
      *reinterpret_cast<float4*>(o0 + g) = make_float4(qa0, qa1, qa2, qa3);
      *reinterpret_cast<float4*>(o1 + g) = make_float4(qb0, qb1, qb2, qb3);
    }
    // ---- phase 2: prefetch [g+8, g+12), compute on B ----
    if (g + 8 < TT) {
#pragma unroll
      for (int i = 0; i < 4; i++) { A0[i] = x0p[g + 8 + i]; A1[i] = x1p[g + 8 + i]; }
    }
    {
      float qa0, qa1, qa2, qa3, qb0, qb1, qb2, qb3;
      qa0 = step(Bb0[0], S0, G0, R0, c);  qb0 = step(Bb1[0], S1, G1, R1, c);
      qa1 = step(Bb0[1], S0, G0, R0, c);  qb1 = step(Bb1[1], S1, G1, R1, c);
      qa2 = step(Bb0[2], S0, G0, R0, c);  qb2 = step(Bb1[2], S1, G1, R1, c);
      qa3 = step(Bb0[3], S0, G0, R0, c);  qb3 = step(Bb1[3], S1, G1, R1, c);
      *reinterpret_cast<float4*>(o0 + g + 4) = make_float4(qa0, qa1, qa2, qa3);
      *reinterpret_cast<float4*>(o1 + g + 4) = make_float4(qb0, qb1, qb2, qb3);
    }
  }

  // Q[b,0]: jnp.roll wrap -> SMS1/GW1 = FINAL states; RS = outs[b,0,2]
  o0[0] = q_final(first0, S0, G0, rs00, c);
  o1[0] = q_final(first1, S1, G1, rs01, c);
}

extern "C" void kernel_launch(void* const* d_in, const int* in_sizes, int n_in,
                              void* d_out, int out_size) {
  const float4* xin = (const float4*)d_in[0];
  int B = out_size / TT;
  int H = B / 2;
  int grid = (H + 31) / 32;
  hirnn_kernel<<<grid, 32>>>(xin,
      (const float*)d_in[1], (const float*)d_in[2], (const float*)d_in[3],
      (const float*)d_in[4], (const float*)d_in[5], (const float*)d_in[6],
      (const float*)d_in[7], (const float*)d_in[8], (const float*)d_in[9],
      (const float*)d_in[10],
      (float*)d_out, B);
}

// round 5
// speedup vs baseline: 1.7133x; 1.7133x over previous
#include <cuda_runtime.h>
#include <cstdint>

#define TT 2048

__device__ __forceinline__ float ex2_ap (float x){ float r; asm("ex2.approx.f32 %0, %1;"  : "=f"(r) : "f"(x)); return r; }
__device__ __forceinline__ float rcp_ap (float x){ float r; asm("rcp.approx.f32 %0, %1;"  : "=f"(r) : "f"(x)); return r; }
__device__ __forceinline__ float sqrt_ap(float x){ float r; asm("sqrt.approx.f32 %0, %1;" : "=f"(r) : "f"(x)); return r; }
__device__ __forceinline__ float clampf(float x, float lo, float hi){ return fminf(fmaxf(x, lo), hi); }
__device__ __forceinline__ float relu(float x){ return fmaxf(x, 0.f); }

struct Consts {
  float insc, Cc, Sc, Sinv, kexp, sub, crak, rk, lg, kr, ls;
};

// One scan step. Produces the 7-float tuple needed to emit Q later.
__device__ __forceinline__ void scan_step(float4 v, float rcpR,
    float& S, float& G, float& R,
    float& tx6, float& tRS, float& tU, float& tBAS, float& tkrR, float& trcp, float& tA,
    const Consts& c)
{
  float Prec = v.x, PET = v.y, RSmax = v.z, Area = v.w;

  // interception: all operands >= 0, relu's provably redundant
  float INTC = fminf(fminf(c.insc, PET), Prec);
  float INR  = Prec - INTC;
  float POT  = PET  - INTC;

  // SMS recurrence chain
  float SMS1c = fmaxf(fminf(S, c.Sc), 0.f);
  float ratio = SMS1c * c.Sinv;
  float infil = c.Cc * ex2_ap(c.kexp * SMS1c);
  float sr = c.sub  * ratio;
  float cr = c.crak * ratio;
  float ETS  = fminf(POT, 10.f * ratio);
  float base = SMS1c - ETS;

  float RMO  = fminf(INR, infil);
  float IRUN = INR - RMO;
  float SRUN = sr * RMO;
  float RmS  = (1.f - sr) * RMO;
  float REC  = cr * RmS;
  float SMF  = (1.f - cr) * RmS;
  float SMSn = base + SMF;

  // recharge + gw
  float xr   = SMSn - c.Sc;
  float RECn = REC + relu(xr);
  float BAS  = c.rk * relu(G);
  float GWn  = (G - c.lg - BAS) + RECn;

  // release with incoming RS
  float inflow = (IRUN + SRUN + BAS) * Area;
  float x5  = R + inflow - RSmax;
  float Qor = relu(x5);
  float r5  = relu(R) * rcpR;
  float p5  = r5 * sqrt_ap(r5);
  float krR = c.kr * RSmax;
  float Qir = (x5 > 0.f) ? krR : (c.kr * R * p5);
  float RSn = R + inflow - Qor - Qir;   // relu(inflow)==inflow (all terms >=0)

  // save tuple for delayed pass-2 Q
  tx6 = RSn + inflow - RSmax;
  tRS = RSn; tU = IRUN + SRUN; tBAS = BAS; tkrR = krR; trcp = rcpR; tA = 1.f - Area;

  S = SMSn; G = GWn; R = RSn;
}

// Delayed pass-2 Q from saved tuple (valid for t>=1; t==0 patched later).
__device__ __forceinline__ float q_out(float x6, float RSn, float U, float BAS,
                                       float krR, float rcpR, float onemA, const Consts& c)
{
  float Qor2 = relu(x6);
  float r6 = relu(RSn) * rcpR;
  float p6 = r6 * sqrt_ap(r6);
  float Qir2 = (x6 > 0.f) ? krR : (c.kr * RSn * p6);
  float drarg = U * onemA + Qir2 + Qor2 - c.ls;
  return relu(relu(drarg) + BAS * onemA);
}

// Full pass-2 Q for t==0: rolled SMS/GW = FINAL states, RS = outs[b,0,2]
__device__ __forceinline__ float q_final(float4 v, float SMS1r, float GW1r, float RSr, const Consts& c)
{
  float Prec = v.x, PET = v.y, RSmax = v.z, Area = v.w;
  float INTC = fminf(fminf(c.insc, PET), Prec);
  float INR  = Prec - INTC;
  float SMS1c = fmaxf(fminf(SMS1r, c.Sc), 0.f);
  float infil = c.Cc * ex2_ap(c.kexp * SMS1c);
  float RMO = fminf(INR, infil);
  float IRUN = INR - RMO;
  float ratio = SMS1c * c.Sinv;
  float SRUN = c.sub * ratio * RMO;
  float BAS = c.rk * relu(GW1r);
  float inflow = (IRUN + SRUN + BAS) * Area;
  float x5 = RSr + inflow - RSmax;
  float Qor = relu(x5);
  float r = relu(RSr) * rcp_ap(RSmax);
  float pw = r * sqrt_ap(r);
  float Qir = (x5 > 0.f) ? (c.kr * RSmax) : (c.kr * RSr * pw);
  float drarg = (SRUN + IRUN) * (1.f - Area) + Qir + Qor - c.ls;
  float DR = relu(drarg);
  float GD = BAS * (1.f - Area);
  return relu(DR + GD);
}

__global__ void __launch_bounds__(32, 1)
hirnn_kernel(const float4* __restrict__ xin_all,
             const float* __restrict__ pINSC, const float* __restrict__ pCOEFF,
             const float* __restrict__ pSQ,   const float* __restrict__ pSMSC,
             const float* __restrict__ pSUB,  const float* __restrict__ pCRAK,
             const float* __restrict__ pRecK, const float* __restrict__ pKr,
             const float* __restrict__ pLG,   const float* __restrict__ pLS,
             float* __restrict__ out, int B)
{
  int b = blockIdx.x * 32 + threadIdx.x;
  if (b >= B) return;

  Consts c;
  c.insc = clampf(pINSC[0] * 5.f, 0.5f, 5.f);
  c.Cc   = clampf(pCOEFF[0] * 400.f, 50.f, 400.f);
  float qv = clampf(pSQ[0] * 6.f, 0.f, 6.f);
  c.Sc   = clampf(pSMSC[0] * 500.f, 50.f, 500.f);
  c.Sinv = 1.f / c.Sc;
  c.kexp = -qv * c.Sinv * 1.4426950408889634f;   // exp(-q*s/S) == exp2(kexp*s)
  c.sub  = clampf(pSUB[0], 0.f, 1.f);
  c.crak = clampf(pCRAK[0], 0.f, 1.f);
  c.rk   = clampf(pRecK[0] * 0.3f, 0.003f, 0.3f);
  c.lg   = clampf(pLG[0] * 0.1f, 0.001f, 0.1f);
  c.kr   = clampf(pKr[0] * 0.1f, 0.01f, 0.1f);
  c.ls   = clampf(pLS[0] * 10.f, 0.01f, 10.f);

  const float4* __restrict__ xin = xin_all + (size_t)b * TT;
  float* __restrict__ op = out + (size_t)b * TT;

  float S = 0.f, G = 0.f, R = 0.f;
  float rs0 = 0.f;

  float4 bufA[4], bufB[4];
#pragma unroll
  for (int i = 0; i < 4; i++) bufA[i] = xin[i];
  float4 first = bufA[0];

  // tuple sets A and B (7 floats x 4 steps each)
  float Ax6[4], ARS[4], AU[4], ABAS[4], AkrR[4], Arcp[4], AA[4];
  float Bx6[4], BRS[4], BU[4], BBAS[4], BkrR[4], Brcp[4], BA[4];

  for (int g = 0; g < TT; g += 8) {
    // ---- phase A: scan steps [g, g+4) from bufA -> tupA; emit Q for [g-4, g) from tupB ----
    {
#pragma unroll
      for (int i = 0; i < 4; i++) bufB[i] = xin[g + 4 + i];   // prefetch next group
      float rc[4];
#pragma unroll
      for (int i = 0; i < 4; i++) rc[i] = rcp_ap(bufA[i].z);  // input-only, off-chain
#pragma unroll
      for (int i = 0; i < 4; i++)
        scan_step(bufA[i], rc[i], S, G, R,
                  Ax6[i], ARS[i], AU[i], ABAS[i], AkrR[i], Arcp[i], AA[i], c);
      if (g == 0) {
        rs0 = ARS[0];
      } else {
        float q0 = q_out(Bx6[0], BRS[0], BU[0], BBAS[0], BkrR[0], Brcp[0], BA[0], c);
        float q1 = q_out(Bx6[1], BRS[1], BU[1], BBAS[1], BkrR[1], BA[1] , Brcp[1], c); // placeholder avoided below
        // (note: correct arg order enforced in the line above? keep explicit:)
        q1 = q_out(Bx6[1], BRS[1], BU[1], BBAS[1], BkrR[1], Brcp[1], BA[1], c);
        float q2 = q_out(Bx6[2], BRS[2], BU[2], BBAS[2], BkrR[2], Brcp[2], BA[2], c);
        float q3 = q_out(Bx6[3], BRS[3], BU[3], BBAS[3], BkrR[3], Brcp[3], BA[3], c);
        *reinterpret_cast<float4*>(op + g - 4) = make_float4(q0, q1, q2, q3);
      }
    }
    // ---- phase B: scan steps [g+4, g+8) from bufB -> tupB; emit Q for [g, g+4) from tupA ----
    {
      if (g + 8 < TT) {
#pragma unroll
        for (int i = 0; i < 4; i++) bufA[i] = xin[g + 8 + i];
      }
      float rc[4];
#pragma unroll
      for (int i = 0; i < 4; i++) rc[i] = rcp_ap(bufB[i].z);
#pragma unroll
      for (int i = 0; i < 4; i++)
        scan_step(bufB[i], rc[i], S, G, R,
                  Bx6[i], BRS[i], BU[i], BBAS[i], BkrR[i], Brcp[i], BA[i], c);
      float q0 = q_out(Ax6[0], ARS[0], AU[0], ABAS[0], AkrR[0], Arcp[0], AA[0], c);
      float q1 = q_out(Ax6[1], ARS[1], AU[1], ABAS[1], AkrR[1], Arcp[1], AA[1], c);
      float q2 = q_out(Ax6[2], ARS[2], AU[2], ABAS[2], AkrR[2], Arcp[2], AA[2], c);
      float q3 = q_out(Ax6[3], ARS[3], AU[3], ABAS[3], AkrR[3], Arcp[3], AA[3], c);
      *reinterpret_cast<float4*>(op + g) = make_float4(q0, q1, q2, q3);
    }
  }

  // tail: Q for the last group (steps TT-4..TT-1) held in tupB
  {
    float q0 = q_out(Bx6[0], BRS[0], BU[0], BBAS[0], BkrR[0], Brcp[0], BA[0], c);
    float q1 = q_out(Bx6[1], BRS[1], BU[1], BBAS[1], BkrR[1], Brcp[1], BA[1], c);
    float q2 = q_out(Bx6[2], BRS[2], BU[2], BBAS[2], BkrR[2], Brcp[2], BA[2], c);
    float q3 = q_out(Bx6[3], BRS[3], BU[3], BBAS[3], BkrR[3], Brcp[3], BA[3], c);
    *reinterpret_cast<float4*>(op + TT - 4) = make_float4(q0, q1, q2, q3);
  }

  // Q[b,0]: jnp.roll wrap -> SMS1/GW1 = FINAL states; RS = outs[b,0,2]
  op[0] = q_final(first, S, G, rs0, c);
}

extern "C" void kernel_launch(void* const* d_in, const int* in_sizes, int n_in,
                              void* d_out, int out_size) {
  const float4* xin = (const float4*)d_in[0];
  int B = out_size / TT;
  int grid = (B + 31) / 32;
  hirnn_kernel<<<grid, 32>>>(xin,
      (const float*)d_in[1], (const float*)d_in[2], (const float*)d_in[3],
      (const float*)d_in[4], (const float*)d_in[5], (const float*)d_in[6],
      (const float*)d_in[7], (const float*)d_in[8], (const float*)d_in[9],
      (const float*)d_in[10],
      (float*)d_out, B);
}

// round 7
// speedup vs baseline: 1.8953x; 1.1062x over previous
#include <cuda_runtime.h>
#include <cstdint>

#define TT 2048
#define UNR 8

__device__ __forceinline__ float ex2_ap (float x){ float r; asm("ex2.approx.f32 %0, %1;"   : "=f"(r) : "f"(x)); return r; }
__device__ __forceinline__ float rcp_ap (float x){ float r; asm("rcp.approx.f32 %0, %1;"   : "=f"(r) : "f"(x)); return r; }
__device__ __forceinline__ float sqrt_ap(float x){ float r; asm("sqrt.approx.f32 %0, %1;"  : "=f"(r) : "f"(x)); return r; }
__device__ __forceinline__ float rsq_ap (float x){ float r; asm("rsqrt.approx.f32 %0, %1;" : "=f"(r) : "f"(x)); return r; }
__device__ __forceinline__ float clampf(float x, float lo, float hi){ return fminf(fmaxf(x, lo), hi); }
__device__ __forceinline__ float relu(float x){ return fmaxf(x, 0.f); }

struct Consts {
  float insc, Sc, Sinv, kexp, lCc, sub, crak, rk, lg, kr, ls;
};

// Full pass-2 Q for t==0: rolled SMS/GW = FINAL states, RS = outs[b,0,2]
__device__ __forceinline__ float q_final(float4 v, float SMS1r, float GW1r, float RSr, const Consts& c)
{
  float Prec = v.x, PET = v.y, RSmax = v.z, Area = v.w;
  float INTC = fminf(fminf(c.insc, PET), Prec);
  float INR  = Prec - INTC;
  float SMS1c = fmaxf(fminf(SMS1r, c.Sc), 0.f);
  float infil = ex2_ap(fmaf(c.kexp, SMS1c, c.lCc));
  float RMO = fminf(INR, infil);
  float IRUN = INR - RMO;
  float ratio = SMS1c * c.Sinv;
  float SRUN = c.sub * ratio * RMO;
  float BAS = c.rk * relu(GW1r);
  float inflow = (IRUN + SRUN + BAS) * Area;
  float x5 = RSr + inflow - RSmax;
  float Qor = relu(x5);
  float r = relu(RSr) * rcp_ap(RSmax);
  float pw = r * sqrt_ap(r);
  float Qir = (x5 > 0.f) ? (c.kr * RSmax) : (c.kr * RSr * pw);
  float drarg = (SRUN + IRUN) * (1.f - Area) + Qir + Qor - c.ls;
  float DR = relu(drarg);
  float GD = BAS * (1.f - Area);
  return relu(DR + GD);
}

// One fused step: scan update + pass-2 Q (valid t>=1; t==0 patched later).
// Carries sqrt(RS) as extra state so its latency hides under the next spine.
__device__ __forceinline__ float step(float4 v, float& S, float& G, float& R, float& sqR,
                                      const Consts& c)
{
  float Prec = v.x, PET = v.y, RSmax = v.z, Area = v.w;

  // input-only (off all chains)
  float INTC = fminf(fminf(c.insc, PET), Prec);
  float INR  = Prec - INTC;
  float POT  = PET  - INTC;
  float u    = rsq_ap(RSmax);
  float crs  = c.kr * (u * u * u);      // kr * RSmax^{-1.5}
  float krR  = c.kr * RSmax;
  float RSov = RSmax - krR;             // RSmax*(1-kr): RSn in overflow case
  float onemA = 1.f - Area;

  // ---- SMS spine: min(S,Sc) -> fma -> ex2 -> fma -> min ----
  float SMS1c = fminf(S, c.Sc);                 // >=0 invariant (proven)
  float infil = ex2_ap(fmaf(c.kexp, SMS1c, c.lCc));
  float ratio = SMS1c * c.Sinv;                 // side chain, ready before ex2
  float sr  = c.sub  * ratio;
  float cr  = c.crak * ratio;
  float msr = 1.f - sr;
  float m   = msr * (1.f - cr);
  float mcr = cr * msr;
  float ETS  = fminf(POT, 10.f * ratio);
  float base = SMS1c - ETS;
  float w = fmaf(m, INR,   base);
  float z = fmaf(m, infil, base);
  float SMSn = fminf(w, z);                     // == base + m*min(INR,infil) exactly

  // off-spine
  float RMO  = fminf(INR, infil);
  float U    = fmaf(-msr, RMO, INR);            // IRUN + SRUN
  float REC  = mcr * RMO;
  float RECn = REC + relu(SMSn - c.Sc);

  // GW (short chain)
  float reluG = relu(G);
  float BAS = c.rk * reluG;
  float GWn = ((G - c.lg) + RECn) - BAS;

  // RS (short chain; sqrt(R) carried from previous step)
  float inflow = (U + BAS) * Area;
  float Rpi = R + inflow;
  float x5  = Rpi - RSmax;
  float t1  = (crs * sqR) * R;                  // kr * R^1.5 / RSmax^1.5
  float RSn_no = fmaf(-t1, R, Rpi);             // R + inflow - kr*R*(R/RSmax)^1.5
  float RSn = (x5 > 0.f) ? RSov : RSn_no;
  float sqn = sqrt_ap(RSn);                     // for next step + q_out (RSn>=0 proven)

  // pass-2 Q with POST-step RS (zero extra MUFUs)
  float x6 = RSn + inflow - RSmax;
  float Qor2 = relu(x6);
  float Qir2 = (x6 > 0.f) ? krR : ((crs * RSn) * (RSn * sqn));  // kr*RSn*(RSn/RSmax)^1.5
  float drarg = fmaf(U, onemA, (Qir2 + Qor2) - c.ls);
  float Q = relu(relu(drarg) + BAS * onemA);

  S = SMSn; G = GWn; R = RSn; sqR = sqn;
  return Q;
}

__global__ void __launch_bounds__(32, 1)
hirnn_kernel(const float4* __restrict__ xin_all,
             const float* __restrict__ pINSC, const float* __restrict__ pCOEFF,
             const float* __restrict__ pSQ,   const float* __restrict__ pSMSC,
             const float* __restrict__ pSUB,  const float* __restrict__ pCRAK,
             const float* __restrict__ pRecK, const float* __restrict__ pKr,
             const float* __restrict__ pLG,   const float* __restrict__ pLS,
             float* __restrict__ out, int B)
{
  int b = blockIdx.x * 32 + threadIdx.x;
  if (b >= B) return;

  Consts c;
  c.insc = clampf(pINSC[0] * 5.f, 0.5f, 5.f);
  float Cc = clampf(pCOEFF[0] * 400.f, 50.f, 400.f);
  float qv = clampf(pSQ[0] * 6.f, 0.f, 6.f);
  c.Sc   = clampf(pSMSC[0] * 500.f, 50.f, 500.f);
  c.Sinv = 1.f / c.Sc;
  c.kexp = -qv * c.Sinv * 1.4426950408889634f;   // exp(-q*s/S)*Cc == exp2(kexp*s + lCc)
  c.lCc  = log2f(Cc);
  c.sub  = clampf(pSUB[0], 0.f, 1.f);
  c.crak = clampf(pCRAK[0], 0.f, 1.f);
  c.rk   = clampf(pRecK[0] * 0.3f, 0.003f, 0.3f);
  c.lg   = clampf(pLG[0] * 0.1f, 0.001f, 0.1f);
  c.kr   = clampf(pKr[0] * 0.1f, 0.01f, 0.1f);
  c.ls   = clampf(pLS[0] * 10.f, 0.01f, 10.f);

  const float4* __restrict__ xin = xin_all + (size_t)b * TT;
  float* __restrict__ op = out + (size_t)b * TT;

  float S = 0.f, G = 0.f, R = 0.f, sqR = 0.f;
  float rs0 = 0.f;

  float4 buf[UNR], nbuf[UNR];
#pragma unroll
  for (int i = 0; i < UNR; i++) buf[i] = xin[i];
  float4 first = buf[0];

  float qb0 = 0.f, qb1 = 0.f, qb2 = 0.f, qb3 = 0.f;

  for (int g = 0; g < TT; g += UNR) {
    if (g + UNR < TT) {
#pragma unroll
      for (int i = 0; i < UNR; i++) nbuf[i] = xin[g + UNR + i];
    }
#pragma unroll
    for (int i = 0; i < UNR; i++) {
      float Q = step(buf[i], S, G, R, sqR, c);
      if (g + i == 0) rs0 = R;
      if      ((i & 3) == 0) qb0 = Q;
      else if ((i & 3) == 1) qb1 = Q;
      else if ((i & 3) == 2) qb2 = Q;
      else {
        qb3 = Q;
        *reinterpret_cast<float4*>(op + g + (i - 3)) = make_float4(qb0, qb1, qb2, qb3);
      }
    }
#pragma unroll
    for (int i = 0; i < UNR; i++) buf[i] = nbuf[i];
  }

  // Q[b,0]: jnp.roll wrap -> SMS1/GW1 = FINAL states; RS = outs[b,0,2]
  op[0] = q_final(first, S, G, rs0, c);
}

extern "C" void kernel_launch(void* const* d_in, const int* in_sizes, int n_in,
                              void* d_out, int out_size) {
  const float4* xin = (const float4*)d_in[0];
  int B = out_size / TT;
  int grid = (B + 31) / 32;
  hirnn_kernel<<<grid, 32>>>(xin,
      (const float*)d_in[1], (const float*)d_in[2], (const float*)d_in[3],
      (const float*)d_in[4], (const float*)d_in[5], (const float*)d_in[6],
      (const float*)d_in[7], (const float*)d_in[8], (const float*)d_in[9],
      (const float*)d_in[10],
      (float*)d_out, B);
}